// round 5
// baseline (speedup 1.0000x reference)
#include <cuda_runtime.h>

#define MAXB   16
#define MAXA   131072
#define MAXBLK 512
#define TPB    256
#define MAXM   64

__device__ float g_w[MAXB * MAXA];          // per-anchor streaming weight (NEGK or 0)
__device__ float g_partCa[MAXB * MAXBLK];   // kernel A: one-hot corrections
__device__ float g_partR [MAXB * MAXBLK];   // kernel A: reg loss partials
__device__ int   g_partP [MAXB * MAXBLK];   // kernel A: positive counts
__device__ float g_partCb[MAXB * MAXBLK];   // kernel B: streaming cls partials
__device__ unsigned int g_done = 0;

#define NEGK (-0.75f * 0.693147180559945f)  /* -(1-alpha) * ln2 */
#define POSK (-0.25f * 0.693147180559945f)  /* -alpha * ln2     */

// ---------------- Kernel A: anchor assignment ----------------
__global__ __launch_bounds__(TPB) void focal_assign(
    const float* __restrict__ cls,   // [B, A, K]
    const float* __restrict__ reg,   // [B, A, 4]
    const float* __restrict__ anc,   // [1, A, 4]
    const float* __restrict__ ann,   // [B, M, 5]
    int A, int K, int M)
{
    const int b   = blockIdx.y;
    const int tid = threadIdx.x;

    __shared__ float s_gx1[MAXM], s_gy1[MAXM], s_gx2[MAXM], s_gy2[MAXM];
    __shared__ float s_garea[MAXM], s_glab[MAXM];
    __shared__ float s_redC[TPB], s_redR[TPB];
    __shared__ int   s_redP[TPB];

    if (tid < M && tid < MAXM) {
        const float* g = ann + ((size_t)b * M + tid) * 5;
        float x1 = g[0], y1 = g[1], x2 = g[2], y2 = g[3], lab = g[4];
        if (lab == -1.0f) {                       // padded GT: zero-overlap sentinel
            x1 = 3.0e37f; x2 = -3.0e37f; y1 = 0.f; y2 = 0.f;
        }
        s_gx1[tid] = x1; s_gy1[tid] = y1; s_gx2[tid] = x2; s_gy2[tid] = y2;
        s_garea[tid] = (lab == -1.0f) ? 0.f : (x2 - x1) * (y2 - y1);
        s_glab[tid] = lab;
    }
    __syncthreads();

    float accC = 0.f, accR = 0.f;
    int   accP = 0;

    for (int a = blockIdx.x * TPB + tid; a < A; a += gridDim.x * TPB) {
        float4 av = __ldg(((const float4*)anc) + a);
        float aw = av.z - av.x;
        float ah = av.w - av.y;
        float aarea = aw * ah;

        // best IoU as (inter, ua) pair; strict > keeps first-argmax tie semantics
        float bi = 0.f, bu = 1.f;
        int   bm = -1;
        int mlim = (M < MAXM) ? M : MAXM;
        #pragma unroll 4
        for (int m = 0; m < mlim; m++) {
            float iw = fminf(av.z, s_gx2[m]) - fmaxf(av.x, s_gx1[m]);
            float ih = fminf(av.w, s_gy2[m]) - fmaxf(av.y, s_gy1[m]);
            float inter = fmaxf(iw, 0.f) * fmaxf(ih, 0.f);
            float ua = fmaxf(aarea + s_garea[m] - inter, 1e-8f);
            if (inter * bu > bi * ua) { bi = inter; bu = ua; bm = m; }
        }

        bool pos = (bm >= 0) && (bi >= 0.5f * bu);
        bool neg = (bi < 0.4f * bu);
        g_w[b * MAXA + a] = (pos || neg) ? NEGK : 0.f;

        if (pos) {
            accP++;
            float gx1 = s_gx1[bm], gy1 = s_gy1[bm];
            float gx2 = s_gx2[bm], gy2 = s_gy2[bm];
            float gwr = gx2 - gx1, ghr = gy2 - gy1;
            float acx = av.x + 0.5f * aw, acy = av.y + 0.5f * ah;
            float gcx = gx1 + 0.5f * gwr, gcy = gy1 + 0.5f * ghr;
            float gw = fmaxf(gwr, 1.f), gh = fmaxf(ghr, 1.f);
            float t0 = ((gcx - acx) / aw) / 0.1f;
            float t1 = ((gcy - acy) / ah) / 0.1f;
            float t2 = logf(gw / aw) / 0.2f;
            float t3 = logf(gh / ah) / 0.2f;
            float4 rv = __ldg(((const float4*)reg) + (size_t)b * A + a);
            float d0 = fabsf(t0 - rv.x);
            float d1 = fabsf(t1 - rv.y);
            float d2 = fabsf(t2 - rv.z);
            float d3 = fabsf(t3 - rv.w);
            const float TH = 1.0f / 9.0f;
            const float CC = 0.5f / 9.0f;
            accR += (d0 <= TH) ? 4.5f * d0 * d0 : d0 - CC;
            accR += (d1 <= TH) ? 4.5f * d1 * d1 : d1 - CC;
            accR += (d2 <= TH) ? 4.5f * d2 * d2 : d2 - CC;
            accR += (d3 <= TH) ? 4.5f * d3 * d3 : d3 - CC;

            // one-hot lane correction: streaming adds NEGK*c^2*lg2(1-c);
            // replace with positive focal term for the label lane.
            int lab = (int)s_glab[bm];
            float c = __ldg(cls + ((size_t)b * A + a) * K + lab);
            float u = 1.f - c;
            accC += POSK * u * u * __log2f(c) - NEGK * c * c * __log2f(u);
        }
    }

    s_redC[tid] = accC;
    s_redR[tid] = accR;
    s_redP[tid] = accP;
    __syncthreads();
    for (int off = TPB / 2; off > 0; off >>= 1) {
        if (tid < off) {
            s_redC[tid] += s_redC[tid + off];
            s_redR[tid] += s_redR[tid + off];
            s_redP[tid] += s_redP[tid + off];
        }
        __syncthreads();
    }
    if (tid == 0) {
        g_partCa[b * MAXBLK + blockIdx.x] = s_redC[0];
        g_partR [b * MAXBLK + blockIdx.x] = s_redR[0];
        g_partP [b * MAXBLK + blockIdx.x] = s_redP[0];
    }
}

// ---------------- Kernel B: lean streaming + fused finalize ----------------
template<int KT>
__global__ __launch_bounds__(TPB) void focal_stream(
    const float* __restrict__ cls,   // [B, A, K]
    const float* __restrict__ ann,   // [B, M, 5]
    int A, int Kr, int M, int gxA, int nBlkTotal, float* __restrict__ out)
{
    const int K  = (KT > 0) ? KT : Kr;
    const int K4 = K >> 2;
    const int b   = blockIdx.y;
    const int B   = gridDim.y;
    const int tid = threadIdx.x;

    __shared__ float s_red[TPB];
    __shared__ int   s_isLast;
    __shared__ double shC[MAXB], shR[MAXB];

    const float4* cb = (const float4*)(cls + (size_t)b * A * K);
    const float*  wb = g_w + b * MAXA;
    const int total  = A * K4;
    const int stride = gridDim.x * TPB;

    float accC = 0.f;
    #pragma unroll 4
    for (int i = blockIdx.x * TPB + tid; i < total; i += stride) {
        float4 v = __ldcs(cb + i);
        float ww = __ldg(wb + i / K4);           // constexpr K4 -> umulhi+shr
        float l0 = __log2f(1.f - v.x);
        float l1 = __log2f(1.f - v.y);
        float l2 = __log2f(1.f - v.z);
        float l3 = __log2f(1.f - v.w);
        float s = fmaf(v.x * v.x, l0,
                  fmaf(v.y * v.y, l1,
                  fmaf(v.z * v.z, l2, (v.w * v.w) * l3)));
        accC = fmaf(ww, s, accC);
    }
    // scalar tail if K % 4 != 0 (not hit for K=80)
    if (KT == 0) {
        int kRem = K - (K4 << 2);
        if (kRem) {
            const float* cs = cls + (size_t)b * A * K;
            for (int i = blockIdx.x * TPB + tid; i < A * kRem; i += stride) {
                int aL = i / kRem;
                int k  = (K4 << 2) + (i - aL * kRem);
                float c = __ldg(cs + (size_t)aL * K + k);
                accC = fmaf(__ldg(wb + aL), c * c * __log2f(1.f - c), accC);
            }
        }
    }

    s_red[tid] = accC;
    __syncthreads();
    for (int off = TPB / 2; off > 0; off >>= 1) {
        if (tid < off) s_red[tid] += s_red[tid + off];
        __syncthreads();
    }
    if (tid == 0) {
        g_partCb[b * MAXBLK + blockIdx.x] = s_red[0];
        __threadfence();
        unsigned v = atomicAdd(&g_done, 1u);
        s_isLast = (v == (unsigned)(nBlkTotal - 1));
    }
    __syncthreads();

    if (s_isLast) {
        __threadfence();
        const int wrp  = tid >> 5;
        const int lane = tid & 31;
        const int gxB  = gridDim.x;
        if (wrp < B) {
            float c = 0.f, r = 0.f; int p = 0;
            for (int i = lane; i < gxB; i += 32)
                c += g_partCb[wrp * MAXBLK + i];
            for (int i = lane; i < gxA; i += 32) {
                c += g_partCa[wrp * MAXBLK + i];
                r += g_partR [wrp * MAXBLK + i];
                p += g_partP [wrp * MAXBLK + i];
            }
            #pragma unroll
            for (int off = 16; off > 0; off >>= 1) {
                c += __shfl_down_sync(0xffffffffu, c, off);
                r += __shfl_down_sync(0xffffffffu, r, off);
                p += __shfl_down_sync(0xffffffffu, p, off);
            }
            bool hv = false;
            for (int m = lane; m < M; m += 32)
                if (__ldg(ann + ((size_t)wrp * M + m) * 5 + 4) != -1.0f) hv = true;
            unsigned hvb = __ballot_sync(0xffffffffu, hv);
            if (lane == 0) {
                double cv = 0.0, rv = 0.0;
                if (hvb != 0u) cv = (double)c / (double)(p > 1 ? p : 1);
                if (p > 0) {
                    int d = p * 4 > 1 ? p * 4 : 1;
                    rv = (double)r / (double)d;
                }
                shC[wrp] = cv;
                shR[wrp] = rv;
            }
        }
        __syncthreads();
        if (tid == 0) {
            double cs = 0.0, rs = 0.0;
            for (int i = 0; i < B; i++) { cs += shC[i]; rs += shR[i]; }
            out[0] = (float)(cs / (double)B);
            out[1] = (float)(rs / (double)B);
            atomicExch(&g_done, 0u);   // reset for graph replay
        }
    }
}

extern "C" void kernel_launch(void* const* d_in, const int* in_sizes, int n_in,
                              void* d_out, int out_size) {
    const float* cls = (const float*)d_in[0];
    const float* reg = (const float*)d_in[1];
    const float* anc = (const float*)d_in[2];
    const float* ann = (const float*)d_in[3];

    int A = in_sizes[2] / 4;                                        // anchors [1,A,4]
    int B = in_sizes[1] / (A * 4);                                  // regressions [B,A,4]
    int K = (int)((long long)in_sizes[0] / ((long long)A * B));     // cls [B,A,K]
    int M = in_sizes[3] / (B * 5);                                  // annotations [B,M,5]

    // kernel A: anchor assignment
    int nABlocks = (A + TPB - 1) / TPB;
    int gxA = nABlocks < MAXBLK ? nABlocks : MAXBLK;
    focal_assign<<<dim3(gxA, B), TPB>>>(cls, reg, anc, ann, A, K, M);

    // kernel B: streaming (aim ~8 resident blocks/SM across images)
    int gxB = (148 * 8) / (B > 0 ? B : 1);
    if (gxB > MAXBLK) gxB = MAXBLK;
    if (gxB < 1) gxB = 1;
    dim3 gridB(gxB, B);
    if (K == 80)
        focal_stream<80><<<gridB, TPB>>>(cls, ann, A, K, M, gxA, gxB * B, (float*)d_out);
    else
        focal_stream<0><<<gridB, TPB>>>(cls, ann, A, K, M, gxA, gxB * B, (float*)d_out);
}

// round 6
// speedup vs baseline: 1.3279x; 1.3279x over previous
#include <cuda_runtime.h>

#define MAXB   16
#define MAXBLK 128
#define TPB    256
#define MAXM   64

__device__ float g_partC[MAXB * MAXBLK];
__device__ float g_partR[MAXB * MAXBLK];
__device__ int   g_partP[MAXB * MAXBLK];
__device__ unsigned int g_done = 0;

#define NEGK (-0.75f * 0.693147180559945f)  /* -(1-alpha) * ln2 */
#define POSK (-0.25f * 0.693147180559945f)  /* -alpha * ln2     */

template<int KT>
__global__ __launch_bounds__(TPB, 6) void focal_main(
    const float* __restrict__ cls,   // [B, A, K]
    const float* __restrict__ reg,   // [B, A, 4]
    const float* __restrict__ anc,   // [1, A, 4]
    const float* __restrict__ ann,   // [B, M, 5]
    int A, int Kr, int M, int nTiles, int nBlkTotal, float* __restrict__ out)
{
    const int K  = (KT > 0) ? KT : Kr;
    const int K4 = K >> 2;
    const int b   = blockIdx.y;
    const int B   = gridDim.y;
    const int tid = threadIdx.x;

    __shared__ float4 s_box[MAXM];           // x1,y1,x2,y2
    __shared__ float2 s_meta[MAXM];          // area, label
    __shared__ float  s_w[TPB];
    __shared__ float  s_redC[TPB], s_redR[TPB];
    __shared__ int    s_redP[TPB];
    __shared__ int    s_isLast;
    __shared__ double shC[MAXB], shR[MAXB];

    // ---- load & preprocess GT annotations for this image ----
    if (tid < M && tid < MAXM) {
        const float* g = ann + ((size_t)b * M + tid) * 5;
        float x1 = g[0], y1 = g[1], x2 = g[2], y2 = g[3], lab = g[4];
        if (lab == -1.0f) {                      // padded GT: zero-overlap sentinel
            x1 = 3.0e37f; x2 = -3.0e37f; y1 = 0.f; y2 = 0.f;
        }
        s_box[tid]  = make_float4(x1, y1, x2, y2);
        s_meta[tid] = make_float2((lab == -1.0f) ? 0.f : (x2 - x1) * (y2 - y1), lab);
    }
    __syncthreads();

    float accC = 0.f, accR = 0.f;
    int   accP = 0;
    const int mlim = (M < MAXM) ? M : MAXM;

    for (int tile = blockIdx.x; tile < nTiles; tile += gridDim.x) {
        const int a0 = tile * TPB;
        const int a  = a0 + tid;

        // ---- phase 1: per-anchor IoU argmax -> weight, reg loss, pos correction ----
        float w = 0.f;
        if (a < A) {
            float4 av = __ldg(((const float4*)anc) + a);
            float aarea = (av.z - av.x) * (av.w - av.y);

            // best IoU as (inter, ua) pair; strict > keeps first-argmax tie semantics
            float bi = 0.f, bu = 1.f;
            int   bm = -1;
            #pragma unroll 4
            for (int m = 0; m < mlim; m++) {
                float4 gb = s_box[m];
                float2 gm = s_meta[m];
                float iw = fminf(av.z, gb.z) - fmaxf(av.x, gb.x);
                float ih = fminf(av.w, gb.w) - fmaxf(av.y, gb.y);
                float inter = fmaxf(iw, 0.f) * fmaxf(ih, 0.f);
                float ua = fmaxf(aarea + gm.x - inter, 1e-8f);
                if (inter * bu > bi * ua) { bi = inter; bu = ua; bm = m; }
            }

            bool pos = (bm >= 0) && (bi >= 0.5f * bu);
            bool neg = (bi < 0.4f * bu);
            w = (pos || neg) ? NEGK : 0.f;

            if (pos) {
                accP++;
                float4 gb = s_box[bm];
                float aw = av.z - av.x;
                float ah = av.w - av.y;
                float gwr = gb.z - gb.x, ghr = gb.w - gb.y;
                float acx = av.x + 0.5f * aw, acy = av.y + 0.5f * ah;
                float gcx = gb.x + 0.5f * gwr, gcy = gb.y + 0.5f * ghr;
                float gw = fmaxf(gwr, 1.f), gh = fmaxf(ghr, 1.f);
                float t0 = ((gcx - acx) / aw) / 0.1f;
                float t1 = ((gcy - acy) / ah) / 0.1f;
                float t2 = logf(gw / aw) / 0.2f;
                float t3 = logf(gh / ah) / 0.2f;
                float4 rv = __ldg(((const float4*)reg) + (size_t)b * A + a);
                float d0 = fabsf(t0 - rv.x);
                float d1 = fabsf(t1 - rv.y);
                float d2 = fabsf(t2 - rv.z);
                float d3 = fabsf(t3 - rv.w);
                const float TH = 1.0f / 9.0f;
                const float CC = 0.5f / 9.0f;
                accR += (d0 <= TH) ? 4.5f * d0 * d0 : d0 - CC;
                accR += (d1 <= TH) ? 4.5f * d1 * d1 : d1 - CC;
                accR += (d2 <= TH) ? 4.5f * d2 * d2 : d2 - CC;
                accR += (d3 <= TH) ? 4.5f * d3 * d3 : d3 - CC;

                // one-hot lane correction: streaming adds NEGK*c^2*lg2(1-c);
                // replace with positive focal term.
                int lab = (int)s_meta[bm].y;
                float c = __ldg(cls + ((size_t)b * A + a) * K + lab);
                float u = 1.f - c;
                accC += POSK * u * u * __log2f(c) - NEGK * c * c * __log2f(u);
            }
        }
        s_w[tid] = w;
        __syncthreads();

        // ---- phase 2: branchless coalesced streaming over [a0:a0+256, 0:K] ----
        int nA = A - a0; if (nA > TPB) nA = TPB;
        const float4* cb = (const float4*)(cls + ((size_t)b * A + (size_t)a0) * K);

        if (KT > 0 && nA == TPB) {
            constexpr int ITERS = (KT > 0) ? (KT / 4) : 1;
            #pragma unroll 5
            for (int j = 0; j < ITERS; j++) {
                int i = j * TPB + tid;
                float4 v = __ldcs(cb + i);
                float ww = s_w[i / K4];          // constexpr divisor -> umulhi+shr
                float l0 = __log2f(1.f - v.x);
                float l1 = __log2f(1.f - v.y);
                float l2 = __log2f(1.f - v.z);
                float l3 = __log2f(1.f - v.w);
                float s = fmaf(v.x * v.x, l0,
                          fmaf(v.y * v.y, l1,
                          fmaf(v.z * v.z, l2, (v.w * v.w) * l3)));
                accC = fmaf(ww, s, accC);
            }
        } else {
            int total = nA * K4;
            for (int i = tid; i < total; i += TPB) {
                float4 v = __ldcs(cb + i);
                float ww = s_w[i / K4];
                float l0 = __log2f(1.f - v.x);
                float l1 = __log2f(1.f - v.y);
                float l2 = __log2f(1.f - v.z);
                float l3 = __log2f(1.f - v.w);
                float s = fmaf(v.x * v.x, l0,
                          fmaf(v.y * v.y, l1,
                          fmaf(v.z * v.z, l2, (v.w * v.w) * l3)));
                accC = fmaf(ww, s, accC);
            }
            int kRem = K - (K4 << 2);
            if (kRem) {
                for (int i = tid; i < nA * kRem; i += TPB) {
                    int aL = i / kRem;
                    int k  = (K4 << 2) + (i - aL * kRem);
                    float c = __ldg(cls + ((size_t)b * A + a0 + aL) * K + k);
                    accC = fmaf(s_w[aL], c * c * __log2f(1.f - c), accC);
                }
            }
        }
        __syncthreads();   // protect s_w before next tile rewrites it
    }

    // ---- block reduce & write per-block partials ----
    s_redC[tid] = accC;
    s_redR[tid] = accR;
    s_redP[tid] = accP;
    __syncthreads();
    for (int off = TPB / 2; off > 0; off >>= 1) {
        if (tid < off) {
            s_redC[tid] += s_redC[tid + off];
            s_redR[tid] += s_redR[tid + off];
            s_redP[tid] += s_redP[tid + off];
        }
        __syncthreads();
    }
    if (tid == 0) {
        g_partC[b * MAXBLK + blockIdx.x] = s_redC[0];
        g_partR[b * MAXBLK + blockIdx.x] = s_redR[0];
        g_partP[b * MAXBLK + blockIdx.x] = s_redP[0];
        __threadfence();
        unsigned v = atomicAdd(&g_done, 1u);
        s_isLast = (v == (unsigned)(nBlkTotal - 1));
    }
    __syncthreads();

    // ---- last block: fused finalize (one warp per image) ----
    if (s_isLast) {
        __threadfence();
        const int wrp  = tid >> 5;
        const int lane = tid & 31;
        const int nblk = gridDim.x;
        if (wrp < B) {
            float c = 0.f, r = 0.f; int p = 0;
            for (int i = lane; i < nblk; i += 32) {
                c += g_partC[wrp * MAXBLK + i];
                r += g_partR[wrp * MAXBLK + i];
                p += g_partP[wrp * MAXBLK + i];
            }
            #pragma unroll
            for (int off = 16; off > 0; off >>= 1) {
                c += __shfl_down_sync(0xffffffffu, c, off);
                r += __shfl_down_sync(0xffffffffu, r, off);
                p += __shfl_down_sync(0xffffffffu, p, off);
            }
            bool hv = false;
            for (int m = lane; m < M; m += 32)
                if (__ldg(ann + ((size_t)wrp * M + m) * 5 + 4) != -1.0f) hv = true;
            unsigned hvb = __ballot_sync(0xffffffffu, hv);
            if (lane == 0) {
                double cv = 0.0, rv = 0.0;
                if (hvb != 0u) cv = (double)c / (double)(p > 1 ? p : 1);
                if (p > 0) {
                    int d = p * 4 > 1 ? p * 4 : 1;
                    rv = (double)r / (double)d;
                }
                shC[wrp] = cv;
                shR[wrp] = rv;
            }
        }
        __syncthreads();
        if (tid == 0) {
            double cs = 0.0, rs = 0.0;
            for (int i = 0; i < B; i++) { cs += shC[i]; rs += shR[i]; }
            out[0] = (float)(cs / (double)B);
            out[1] = (float)(rs / (double)B);
            atomicExch(&g_done, 0u);   // reset for graph replay
        }
    }
}

extern "C" void kernel_launch(void* const* d_in, const int* in_sizes, int n_in,
                              void* d_out, int out_size) {
    const float* cls = (const float*)d_in[0];
    const float* reg = (const float*)d_in[1];
    const float* anc = (const float*)d_in[2];
    const float* ann = (const float*)d_in[3];

    int A = in_sizes[2] / 4;                                        // anchors [1,A,4]
    int B = in_sizes[1] / (A * 4);                                  // regressions [B,A,4]
    int K = (int)((long long)in_sizes[0] / ((long long)A * B));     // cls [B,A,K]
    int M = in_sizes[3] / (B * 5);                                  // annotations [B,M,5]

    int nTiles = (A + TPB - 1) / TPB;
    int gx0 = (148 * 6) / (B > 0 ? B : 1);      // 6 resident blocks/SM target
    if (gx0 < 1) gx0 = 1;
    int tpb = (nTiles + gx0 - 1) / gx0;         // balanced tiles per block
    int gx  = (nTiles + tpb - 1) / tpb;
    if (gx > MAXBLK) gx = MAXBLK;
    if (gx < 1) gx = 1;
    dim3 grid(gx, B);

    if (K == 80)
        focal_main<80><<<grid, TPB>>>(cls, reg, anc, ann, A, K, M, nTiles, gx * B, (float*)d_out);
    else
        focal_main<0><<<grid, TPB>>>(cls, reg, anc, ann, A, K, M, nTiles, gx * B, (float*)d_out);
}